// round 4
// baseline (speedup 1.0000x reference)
#include <cuda_runtime.h>
#include <cstdint>

#define NN 8192
#define PB 256            // threads per rank block (one p per thread)
#define QSPLIT 8
#define QCHUNK (NN/QSPLIT) // 1024
#define TILE 256

// Scratch (allocation-free): partial rank counts [arr][qsplit][p], argsort B, tau, counter.
__device__ unsigned int g_rpart[2][QSPLIT][NN];
__device__ int g_B[NN];
__device__ int g_tau[NN];
__device__ unsigned int g_count;

// Monotone uint32 mapping of float (total order matching float < for finite values)
__device__ __forceinline__ unsigned int fkey(float f) {
    unsigned int u = __float_as_uint(f);
    return (u & 0x80000000u) ? ~u : (u | 0x80000000u);
}

__device__ __forceinline__ unsigned long long make_key(float f, int idx) {
    return (((unsigned long long)fkey(f)) << 13) | (unsigned int)idx;  // idx < 8192 fits 13 bits
}

// K1: partial ranks. grid = (NN/PB, QSPLIT, 2 arrays), block = PB threads.
// r[p] = #{q : key[q] < key[p]}  (exact stable-argsort rank via index tie-break in key)
__global__ void rank_kernel(const float* __restrict__ X, const float* __restrict__ Xh) {
    __shared__ unsigned long long sh[TILE];
    const int arr = blockIdx.z;
    const float* __restrict__ src = arr ? Xh : X;
    const int p = blockIdx.x * PB + threadIdx.x;
    const unsigned long long kp = make_key(src[p], p);
    unsigned int cnt = 0;
    const int q0 = blockIdx.y * QCHUNK;
    for (int t = 0; t < QCHUNK; t += TILE) {
        const int q = q0 + t + threadIdx.x;
        __syncthreads();
        sh[threadIdx.x] = make_key(src[q], q);
        __syncthreads();
        #pragma unroll 16
        for (int j = 0; j < TILE; j++)
            cnt += (sh[j] < kp) ? 1u : 0u;
    }
    g_rpart[arr][blockIdx.y][p] = cnt;
}

// K2: s[p] = sum of partials for X_hat; scatter B[s[p]] = p  (B = argsort(X_hat))
__global__ void scatter_kernel() {
    const int p = blockIdx.x * 256 + threadIdx.x;
    unsigned int s = 0;
    #pragma unroll
    for (int z = 0; z < QSPLIT; z++) s += g_rpart[1][z][p];
    g_B[s] = p;
}

// K3: r[i] = sum of partials for X; tau[i] = B[r[i]]; zero the inversion counter.
__global__ void tau_kernel() {
    const int i = blockIdx.x * 256 + threadIdx.x;
    unsigned int r = 0;
    #pragma unroll
    for (int z = 0; z < QSPLIT; z++) r += g_rpart[0][z][i];
    g_tau[i] = g_B[r];
    if (i == 0 && blockIdx.x == 0) g_count = 0;
}

// K4: inversions of tau over upper-triangular 256x256 tiles.
__global__ void inv_kernel() {
    __shared__ int sh[TILE];
    const int ti = blockIdx.y, tj = blockIdx.x;
    if (tj < ti) return;
    const int vi = g_tau[ti * TILE + threadIdx.x];
    sh[threadIdx.x] = g_tau[tj * TILE + threadIdx.x];
    __syncthreads();
    unsigned int cnt = 0;
    if (ti < tj) {
        #pragma unroll 16
        for (int j = 0; j < TILE; j++)
            cnt += (vi > sh[j]) ? 1u : 0u;
    } else {
        for (int j = threadIdx.x + 1; j < TILE; j++)
            cnt += (vi > sh[j]) ? 1u : 0u;
    }
    cnt = __reduce_add_sync(0xffffffffu, cnt);
    if ((threadIdx.x & 31) == 0) atomicAdd(&g_count, cnt);
}

// K5: ndisordered = 2*inv; out = ndisordered / (n*(n-1)). Double for exactness (inv can exceed 2^24).
__global__ void final_kernel(float* __restrict__ out) {
    double inv = (double)g_count;
    out[0] = (float)(2.0 * inv / ((double)NN * (double)(NN - 1)));
}

extern "C" void kernel_launch(void* const* d_in, const int* in_sizes, int n_in,
                              void* d_out, int out_size) {
    const float* X  = (const float*)d_in[0];
    const float* Xh = (const float*)d_in[1];
    float* out = (float*)d_out;

    dim3 g1(NN / PB, QSPLIT, 2);
    rank_kernel<<<g1, PB>>>(X, Xh);
    scatter_kernel<<<NN / 256, 256>>>();
    tau_kernel<<<NN / 256, 256>>>();
    dim3 g4(NN / TILE, NN / TILE);
    inv_kernel<<<g4, TILE>>>();
    final_kernel<<<1, 1>>>(out);
}